// round 14
// baseline (speedup 1.0000x reference)
#include <cuda_runtime.h>

// Rules_67619965108887: out[b,s,r] = (a_i*b_j)*c_k, r = i*25+j*5+k,
//   a_i=f(x[i]), b_j=f(x[5+j]), c_k=f(x[10+k]), f(v)=(v==0)?1:v.
// Association (a*b)*c matches jnp.prod ascending order -> bitwise equal.
//
// R14: R13 proved occupancy is not the lever (occ 55%, slower). R12 (6.59us,
// 8 pos/warp, grid 1024, regs=32) was register-capped: 8 serial ~60-cyc SHFL
// chains per warp. Same structure, three changes:
//   1) __launch_bounds__(128, 6): reg budget ~85 -> position chains overlap.
//   2) All 8 LDGs batched before any chain (MLP=8).
//   3) Two passes: build all ab[] first, then all rounds -> max independent
//      work between dependent shuffles.
// Zero smem, zero barriers, warp-autonomous. Instruction count unchanged.

constexpr int THREADS    = 128;
constexpr int WARPS      = THREADS / 32;
constexpr int P_PER_WARP = 8;
constexpr int P_PER_CTA  = WARPS * P_PER_WARP;   // 32
constexpr unsigned FULL  = 0xFFFFFFFFu;

__global__ __launch_bounds__(THREADS, 6)
void rules_fired_kernel(const float* __restrict__ x,
                        float* __restrict__ out) {
    const int t    = threadIdx.x;
    const int warp = t >> 5;
    const int lane = t & 31;

    // ---- loop-invariant shuffle sources ----
    // ab builder (meaningful for lane < 25): ij = lane = i*5 + j
    const int i_src = lane / 5;                 // a source lane
    const int b_src = 5 + (lane - 5 * i_src);   // b source lane
    // per-round consumers: r = lane + 32*rd; ij = r/5, k = r%5
    int ab_src[4], c_src[4];
    #pragma unroll
    for (int rd = 0; rd < 4; rd++) {
        const int r  = lane + 32 * rd;
        const int ij = r / 5;
        ab_src[rd] = ij;                        // ij=25 for r>=125: not stored
        c_src[rd]  = 10 + (r - 5 * ij);
    }

    const size_t p0 = ((size_t)blockIdx.x * WARPS + warp) * P_PER_WARP;

    // ---- pass 0: all 8 loads in flight (MLP=8) ----
    float v[P_PER_WARP];
    #pragma unroll
    for (int pp = 0; pp < P_PER_WARP; pp++) {
        float w = 0.0f;
        if (lane < 15) w = x[(p0 + pp) * 15 + lane];   // 60B coalesced
        v[pp] = (w == 0.0f) ? 1.0f : w;                // lanes>=15 -> 1.0
    }

    // ---- pass 1: build all pairwise products (8 independent 2-shfl chains) ----
    float ab[P_PER_WARP];
    #pragma unroll
    for (int pp = 0; pp < P_PER_WARP; pp++) {
        const float a = __shfl_sync(FULL, v[pp], i_src);
        const float b = __shfl_sync(FULL, v[pp], b_src);
        ab[pp] = a * b;                         // lanes 0..24 hold ab[ij]
    }

    // ---- pass 2: rounds (32 independent 1-shfl-pair chains) + stores ----
    #pragma unroll
    for (int pp = 0; pp < P_PER_WARP; pp++) {
        float* o = out + (p0 + pp) * 125;
        #pragma unroll
        for (int rd = 0; rd < 4; rd++) {
            const float abr = __shfl_sync(FULL, ab[pp], ab_src[rd]);
            const float c   = __shfl_sync(FULL, v[pp],  c_src[rd]);
            const float res = abr * c;          // (a*b)*c: exact order
            const int r = lane + 32 * rd;
            if (rd < 3 || r < 125) o[r] = res;  // only last round predicated
        }
    }
}

extern "C" void kernel_launch(void* const* d_in, const int* in_sizes, int n_in,
                              void* d_out, int out_size) {
    const float* x = (const float*)d_in[0];     // (B,S,15) float32, B*S=32768
    // d_in[1] = active_rules (compile-time structure), d_in[2] = epoch
    float* out = (float*)d_out;                 // (B,S,125) float32

    const int total_pos = in_sizes[0] / 15;     // 32768
    const int n_ctas = total_pos / P_PER_CTA;   // 1024

    rules_fired_kernel<<<n_ctas, THREADS>>>(x, out);
}

// round 15
// speedup vs baseline: 1.2043x; 1.2043x over previous
#include <cuda_runtime.h>

// Rules_67619965108887: out[b,s,r] = (a_i*b_j)*c_k, r = i*25+j*5+k,
//   a_i=f(x[i]), b_j=f(x[5+j]), c_k=f(x[10+k]), f(v)=(v==0)?1:v.
// Association (a*b)*c matches jnp.prod ascending order -> bitwise equal.
//
// R15: isolation experiment. Shuffle-family results:
//   R12 interleaved loads, P8, grid1024 -> 6.59us (champion)
//   R13 BATCHED loads,     P4, grid2048 -> 7.23us
//   R14 BATCHED + 2-pass,  P8, grid1024 -> 8.96us
// Front-batched LDGs are the regressor (B300 cross-CTA L1tex-queue
// contention: spr_max grows with MLP_p1). This round: R12's exact
// interleaved structure (load issued right before each position's chain),
// but P_PER_WARP=4 / grid 2048 for finer wave granularity (imbalance
// 14% -> 7%). No smem, no barriers, warp-autonomous.

constexpr int THREADS    = 128;
constexpr int WARPS      = THREADS / 32;
constexpr int P_PER_WARP = 4;
constexpr int P_PER_CTA  = WARPS * P_PER_WARP;   // 16
constexpr unsigned FULL  = 0xFFFFFFFFu;

__global__ __launch_bounds__(THREADS)
void rules_fired_kernel(const float* __restrict__ x,
                        float* __restrict__ out) {
    const int t    = threadIdx.x;
    const int warp = t >> 5;
    const int lane = t & 31;

    // ---- loop-invariant shuffle sources ----
    // ab builder (meaningful for lane < 25): ij = lane = i*5 + j
    const int i_src = lane / 5;                 // a source lane
    const int b_src = 5 + (lane - 5 * i_src);   // b source lane
    // per-round consumers: r = lane + 32*rd; ij = r/5, k = r%5
    int ab_src[4], c_src[4];
    #pragma unroll
    for (int rd = 0; rd < 4; rd++) {
        const int r  = lane + 32 * rd;
        const int ij = r / 5;
        ab_src[rd] = ij;                        // ij=25 for r>=125: not stored
        c_src[rd]  = 10 + (r - 5 * ij);
    }

    const size_t p0 = ((size_t)blockIdx.x * WARPS + warp) * P_PER_WARP;

    // interleaved per-position: load -> chain -> stores (champion pattern)
    #pragma unroll
    for (int pp = 0; pp < P_PER_WARP; pp++) {
        const size_t p = p0 + pp;

        // one coalesced 60-byte load per position; zero->one fix
        float v = 1.0f;
        if (lane < 15) {
            const float w = x[p * 15 + lane];
            v = (w == 0.0f) ? 1.0f : w;
        }

        // lanes 0..24 build their pairwise product ab[ij] = a_i * b_j
        const float a  = __shfl_sync(FULL, v, i_src);
        const float b  = __shfl_sync(FULL, v, b_src);
        const float ab = a * b;

        float* o = out + p * 125;
        #pragma unroll
        for (int rd = 0; rd < 4; rd++) {
            const float abr = __shfl_sync(FULL, ab, ab_src[rd]);
            const float c   = __shfl_sync(FULL, v,  c_src[rd]);
            const float res = abr * c;          // (a*b)*c: exact order
            const int r = lane + 32 * rd;
            if (rd < 3 || r < 125) o[r] = res;  // only last round predicated
        }
    }
}

extern "C" void kernel_launch(void* const* d_in, const int* in_sizes, int n_in,
                              void* d_out, int out_size) {
    const float* x = (const float*)d_in[0];     // (B,S,15) float32, B*S=32768
    // d_in[1] = active_rules (compile-time structure), d_in[2] = epoch
    float* out = (float*)d_out;                 // (B,S,125) float32

    const int total_pos = in_sizes[0] / 15;     // 32768
    const int n_ctas = total_pos / P_PER_CTA;   // 2048

    rules_fired_kernel<<<n_ctas, THREADS>>>(x, out);
}

// round 17
// speedup vs baseline: 1.2973x; 1.0772x over previous
#include <cuda_runtime.h>

// Rules_67619965108887: out[b,s,r] = (a_i*b_j)*c_k, r = i*25+j*5+k,
//   a_i=f(x[i]), b_j=f(x[5+j]), c_k=f(x[10+k]), f(v)=(v==0)?1:v.
// Association (a*b)*c matches jnp.prod ascending order -> bitwise equal.
//
// R16: champion = R12 (warp-autonomous shuffle, interleaved loads, P8,
// grid 1024, 6.59us). Its one exposed cost: each position's LDG is issued at
// the top of its own chain -> serial latency exposure x8 per warp. Batching
// all loads (R14) regressed via cross-CTA L1tex-queue contention
// (oe*MLP_p1 = 7*8 >> 16). Middle path: DEPTH-1 PREFETCH — load pos pp+1
// while computing pp. MLP_p1 ~= 2 -> oe*MLP_p1 ~= 14 < 16 (below the
// contention knee), yet every LDG hides under the previous ~100-cyc chain.
// Everything else identical to champion: no smem, no barriers, STG.32.

constexpr int THREADS    = 128;
constexpr int WARPS      = THREADS / 32;
constexpr int P_PER_WARP = 8;
constexpr int P_PER_CTA  = WARPS * P_PER_WARP;   // 32
constexpr unsigned FULL  = 0xFFFFFFFFu;

__global__ __launch_bounds__(THREADS)
void rules_fired_kernel(const float* __restrict__ x,
                        float* __restrict__ out) {
    const int t    = threadIdx.x;
    const int warp = t >> 5;
    const int lane = t & 31;

    // ---- loop-invariant shuffle sources ----
    // ab builder (meaningful for lane < 25): ij = lane = i*5 + j
    const int i_src = lane / 5;                 // a source lane
    const int b_src = 5 + (lane - 5 * i_src);   // b source lane
    // per-round consumers: r = lane + 32*rd; ij = r/5, k = r%5
    int ab_src[4], c_src[4];
    #pragma unroll
    for (int rd = 0; rd < 4; rd++) {
        const int r  = lane + 32 * rd;
        const int ij = r / 5;
        ab_src[rd] = ij;                        // ij=25 for r>=125: not stored
        c_src[rd]  = 10 + (r - 5 * ij);
    }

    const size_t p0 = ((size_t)blockIdx.x * WARPS + warp) * P_PER_WARP;
    const float* src = x + p0 * 15 + lane;      // lane-strided base
    const bool ld = (lane < 15);

    // ---- prologue: load position 0 ----
    float w = ld ? src[0] : 0.0f;

    #pragma unroll
    for (int pp = 0; pp < P_PER_WARP; pp++) {
        // depth-1 prefetch: next position's load in flight during this chain
        float w_next = 0.0f;
        if (pp + 1 < P_PER_WARP && ld) w_next = src[(pp + 1) * 15];

        const float v = (w == 0.0f) ? 1.0f : w; // zero->one fix (lanes>=15: 1.0)

        // lanes 0..24 build their pairwise product ab[ij] = a_i * b_j
        const float a  = __shfl_sync(FULL, v, i_src);
        const float b  = __shfl_sync(FULL, v, b_src);
        const float ab = a * b;

        float* o = out + (p0 + pp) * 125;
        #pragma unroll
        for (int rd = 0; rd < 4; rd++) {
            const float abr = __shfl_sync(FULL, ab, ab_src[rd]);
            const float c   = __shfl_sync(FULL, v,  c_src[rd]);
            const float res = abr * c;          // (a*b)*c: exact order
            const int r = lane + 32 * rd;
            if (rd < 3 || r < 125) o[r] = res;  // only last round predicated
        }

        w = w_next;
    }
}

extern "C" void kernel_launch(void* const* d_in, const int* in_sizes, int n_in,
                              void* d_out, int out_size) {
    const float* x = (const float*)d_in[0];     // (B,S,15) float32, B*S=32768
    // d_in[1] = active_rules (compile-time structure), d_in[2] = epoch
    float* out = (float*)d_out;                 // (B,S,125) float32

    const int total_pos = in_sizes[0] / 15;     // 32768
    const int n_ctas = total_pos / P_PER_CTA;   // 1024

    rules_fired_kernel<<<n_ctas, THREADS>>>(x, out);
}